// round 16
// baseline (speedup 1.0000x reference)
#include <cuda_runtime.h>
#include <cfloat>

// Batched Chamfer loss: uniform grid, warp-boxed DENSE candidate scan.
// B=16, N=M=4096, 3D Gaussian points.
//
// bin_kernel:  per (set,b): smem-staged coalesced loads, count + shfl-scan +
//              scatter -> cell-sorted folded points (-2x,-2y,-2z,|t|^2).
// solve_kernel: one WARP = 32 consecutive sorted queries. Warp computes its
//              dilated cell bounding box (shfl min/max -> warp-uniform),
//              gathers the box's row segments into a per-warp smem buffer
//              (coalesced), then ONE dense warp-uniform loop: all lanes read
//              the same buf[j] (broadcast LDS) -> brute-force-shaped inner
//              loop. Lane's 3x3x3 cube is inside the box, so d^2 <= H^2-eps
//              is exact; unresolved lanes pushed to tail list.
// tail_kernel: block per (set,b), db staged in smem, one warp per query,
//              lane-strided scan + shfl fminf tree (exact).
// fin1/fin2:   deterministic weighted reduction.

constexpr int   B_    = 16;
constexpr int   N_    = 4096;
constexpr int   G     = 20;
constexpr int   CELLS = G * G * G;          // 8000
constexpr float H     = 0.35f;
constexpr float X0    = -3.5f;              // G*H = 7 -> [-3.5, 3.5]
constexpr float INVH  = 1.0f / H;
constexpr float RES_T = H * H - 1e-4f;

constexpr int BIN_THREADS = 1024;
constexpr int SMEM_CNT  = CELLS * 4;                  // 32000
constexpr int SMEM_PTS  = (N_ * 3 / 4) * 16;          // 3072 float4 = 49152
constexpr int SMEM_BIN  = SMEM_CNT + SMEM_PTS;        // 81152

constexpr int NQ     = 2 * B_ * N_;         // 131072
constexpr int NUNITS = NQ / 32;             // 4096 warp units

constexpr int SW        = 8;                // warps per solve block
constexpr int STHREADS  = SW * 32;          // 256
constexpr int SBLOCKS   = 296;
constexpr int CAP       = 640;              // candidate cap per warp
constexpr int SMEM_SOLVE = SW * CAP * 16;   // 81920

constexpr int TAIL_SMEM = N_ * 16;          // 64 KB

__device__ float4 g_binned[2 * B_ * N_];    // cell-sorted folded points
__device__ int    g_starts[2 * B_ * (CELLS + 1)];
__device__ float  g_res[NQ];
__device__ int    g_tail[2 * B_ * N_];
__device__ int    g_tailcnt[2 * B_];
__device__ int    g_qhead;
__device__ float  g_partial[2 * B_];

__device__ __forceinline__ int cell_of(float v) {
    int c = (int)floorf((v - X0) * INVH);
    return min(max(c, 0), G - 1);
}

// ---------------- binning ----------------

__global__ void __launch_bounds__(BIN_THREADS)
bin_kernel(const float* __restrict__ src, const float* __restrict__ tgt)
{
    extern __shared__ char sm[];
    int*    scnt  = (int*)sm;                      // [CELLS]
    float*  s_f   = (float*)(sm + SMEM_CNT);       // 12288 floats (points)
    __shared__ int s_wsum[32];

    const int sb  = blockIdx.x;                    // set*16 + b
    const int set = sb >> 4, b = sb & 15;
    const float4* __restrict__ g4 =
        (const float4*)((set == 0 ? src : tgt) + (size_t)b * N_ * 3);
    float4* s_p4 = (float4*)s_f;
    const int t = threadIdx.x, lane = t & 31, wid = t >> 5;

    if (sb == 0) {                                 // reset per-replay state
        if (t < 2 * B_) g_tailcnt[t] = 0;
        if (t == 2 * B_) g_qhead = 0;
    }

#pragma unroll
    for (int i = 0; i < 8; ++i) {
        const int c = t * 8 + i;
        if (c < CELLS) scnt[c] = 0;
    }
    // Coalesced staged point load: 3072 float4.
    s_p4[t]        = g4[t];
    s_p4[t + 1024] = g4[t + 1024];
    s_p4[t + 2048] = g4[t + 2048];
    __syncthreads();

    // Each thread owns points 4t..4t+3 (12 consecutive floats).
    int pc[4];
#pragma unroll
    for (int r = 0; r < 4; ++r) {
        const float x = s_f[12 * t + 3 * r + 0];
        const float y = s_f[12 * t + 3 * r + 1];
        const float z = s_f[12 * t + 3 * r + 2];
        pc[r] = (cell_of(z) * G + cell_of(y)) * G + cell_of(x);
        atomicAdd(&scnt[pc[r]], 1);
    }
    __syncthreads();

    // Exclusive scan over CELLS: 8 serial/thread + shfl warp scans.
    int local[8], sum = 0;
#pragma unroll
    for (int i = 0; i < 8; ++i) {
        const int c = t * 8 + i;
        local[i] = (c < CELLS) ? scnt[c] : 0;
        sum += local[i];
    }
    int incl = sum;
#pragma unroll
    for (int off = 1; off < 32; off <<= 1) {
        const int v = __shfl_up_sync(0xffffffffu, incl, off);
        if (lane >= off) incl += v;
    }
    if (lane == 31) s_wsum[wid] = incl;
    __syncthreads();
    if (wid == 0) {
        const int v = s_wsum[lane];
        int inc2 = v;
#pragma unroll
        for (int off = 1; off < 32; off <<= 1) {
            const int u = __shfl_up_sync(0xffffffffu, inc2, off);
            if (lane >= off) inc2 += u;
        }
        s_wsum[lane] = inc2 - v;
    }
    __syncthreads();

    int run = s_wsum[wid] + incl - sum;
    int* starts = g_starts + sb * (CELLS + 1);
#pragma unroll
    for (int i = 0; i < 8; ++i) {
        const int c = t * 8 + i;
        if (c < CELLS) {
            starts[c] = run;
            scnt[c]   = run;                       // becomes write cursor
            run += local[i];
        }
    }
    if (t == 0) starts[CELLS] = N_;
    __syncthreads();

#pragma unroll
    for (int r = 0; r < 4; ++r) {
        const float x = s_f[12 * t + 3 * r + 0];
        const float y = s_f[12 * t + 3 * r + 1];
        const float z = s_f[12 * t + 3 * r + 2];
        const int pos = atomicAdd(&scnt[pc[r]], 1);
        g_binned[sb * N_ + pos] =
            make_float4(-2.0f * x, -2.0f * y, -2.0f * z,
                        x * x + y * y + z * z);
    }
}

// ---------------- solve: warp-boxed dense candidate scan ----------------

#define EVAL(tp) dbest = fminf(dbest, \
    fmaf(qx, (tp).x, fmaf(qy, (tp).y, fmaf(qz, (tp).z, (tp).w))))

__global__ void __launch_bounds__(STHREADS)
solve_kernel()
{
    extern __shared__ float4 s_buf[];              // [SW][CAP]
    const int lane = threadIdx.x & 31;
    float4* buf = s_buf + (threadIdx.x >> 5) * CAP;

    while (true) {
        int u = 0;
        if (lane == 0) u = atomicAdd(&g_qhead, 1);
        u = __shfl_sync(0xffffffffu, u, 0);
        if (u >= NUNITS) break;

        const int qsb  = u >> 7;                   // 128 units per (set,b)
        const int dbsb = qsb ^ 16;
        const int pos  = ((u & 127) << 5) + lane;

        const float4 qt = g_binned[qsb * N_ + pos];
        const float qx = -0.5f * qt.x, qy = -0.5f * qt.y, qz = -0.5f * qt.z;
        const float q2 = qt.w;

        const int cx = cell_of(qx), cy = cell_of(qy), cz = cell_of(qz);

        // Warp bounding box (shfl reductions -> warp-uniform), dilate 1.
        int x0 = cx, x1 = cx, y0 = cy, y1 = cy, z0 = cz, z1 = cz;
#pragma unroll
        for (int off = 16; off > 0; off >>= 1) {
            x0 = min(x0, __shfl_xor_sync(0xffffffffu, x0, off));
            x1 = max(x1, __shfl_xor_sync(0xffffffffu, x1, off));
            y0 = min(y0, __shfl_xor_sync(0xffffffffu, y0, off));
            y1 = max(y1, __shfl_xor_sync(0xffffffffu, y1, off));
            z0 = min(z0, __shfl_xor_sync(0xffffffffu, z0, off));
            z1 = max(z1, __shfl_xor_sync(0xffffffffu, z1, off));
        }
        x0 = max(x0 - 1, 0); x1 = min(x1 + 1, G - 1);
        y0 = max(y0 - 1, 0); y1 = min(y1 + 1, G - 1);
        z0 = max(z0 - 1, 0); z1 = min(z1 + 1, G - 1);

        const int*    __restrict__ starts = g_starts + dbsb * (CELLS + 1);
        const float4* __restrict__ pts    = g_binned + dbsb * N_;

        float dbest = FLT_MAX;                     // folded (= d^2 - q2)
        int C = 0;
        for (int z = z0; z <= z1; ++z)
            for (int y = y0; y <= y1; ++y) {
                const int rb = (z * G + y) * G;
                const int a  = starts[rb + x0];
                const int e  = starts[rb + x1 + 1];
                const int len  = e - a;
                const int take = min(len, CAP - C);
                for (int j = lane; j < take; j += 32)      // coalesced gather
                    buf[C + j] = pts[a + j];
                for (int j = take; j < len; ++j) {          // overflow: uniform
                    const float4 tp = pts[a + j];
                    EVAL(tp);
                }
                C += take;
            }
        __syncwarp();

        // Dense warp-uniform scan: broadcast LDS, pipelined.
#pragma unroll 4
        for (int j = 0; j < C; ++j) {
            const float4 tp = buf[j];
            EVAL(tp);
        }
        __syncwarp();                              // buf reused next unit

        const float d2 = q2 + dbest;
        g_res[qsb * N_ + pos] = fmaxf(d2, 0.0f);   // tail overwrites if needed

        // Warp-aggregated push of unresolved queries.
        const bool unres = !(d2 <= RES_T);
        const unsigned m = __ballot_sync(0xffffffffu, unres);
        if (m) {
            const int leader = __ffs(m) - 1;
            int base = 0;
            if (lane == leader) base = atomicAdd(&g_tailcnt[qsb], __popc(m));
            base = __shfl_sync(0xffffffffu, base, leader);
            if (unres) {
                const int off = __popc(m & ((1u << lane) - 1u));
                g_tail[qsb * N_ + base + off] = pos;
            }
        }
    }
}

// ---------------- tail: dense brute force, one warp per query ----------------

__global__ void __launch_bounds__(STHREADS)
tail_kernel()
{
    extern __shared__ float4 s_db[];               // full db for this (set,b)
    const int sb   = blockIdx.x;
    const int dbsb = sb ^ 16;
    const int tid  = threadIdx.x;
    const int lane = tid & 31, wid = tid >> 5;

    for (int i = tid; i < N_; i += STHREADS)
        s_db[i] = g_binned[dbsb * N_ + i];
    __syncthreads();

    const int n = g_tailcnt[sb];
    for (int j = wid; j < n; j += SW) {
        const int pos = g_tail[sb * N_ + j];
        const float4 qt = g_binned[sb * N_ + pos];
        const float qx = -0.5f * qt.x, qy = -0.5f * qt.y, qz = -0.5f * qt.z;

        float m = FLT_MAX;
#pragma unroll 4
        for (int k = lane; k < N_; k += 32) {
            const float4 tp = s_db[k];
            m = fminf(m, fmaf(qx, tp.x, fmaf(qy, tp.y, fmaf(qz, tp.z, tp.w))));
        }
#pragma unroll
        for (int off = 16; off > 0; off >>= 1)
            m = fminf(m, __shfl_xor_sync(0xffffffffu, m, off));
        if (lane == 0)
            g_res[sb * N_ + pos] = fmaxf(qt.w + m, 0.0f);
    }
}

// ---------------- finalize ----------------

__global__ void __launch_bounds__(256)
fin1_kernel(const float* __restrict__ weights)
{
    const int sb = blockIdx.x, t = threadIdx.x;
    const float4* __restrict__ r4 = (const float4*)(g_res + sb * N_);
    float a = 0.0f;
#pragma unroll
    for (int k = 0; k < 4; ++k) {
        const float4 v = r4[t + k * 256];
        a += (v.x + v.y) + (v.z + v.w);
    }
    __shared__ float s[256];
    s[t] = a;
    __syncthreads();
#pragma unroll
    for (int st = 128; st > 0; st >>= 1) {
        if (t < st) s[t] += s[t + st];
        __syncthreads();
    }
    if (t == 0) g_partial[sb] = s[0] * weights[sb & 15];
}

__global__ void fin2_kernel(float* __restrict__ out)
{
    const int lane = threadIdx.x;
    float v = g_partial[lane];
#pragma unroll
    for (int off = 16; off > 0; off >>= 1)
        v += __shfl_xor_sync(0xffffffffu, v, off);
    if (lane == 0) out[0] = v * (1.0f / (16.0f * 4096.0f));
}

extern "C" void kernel_launch(void* const* d_in, const int* in_sizes, int n_in,
                              void* d_out, int out_size)
{
    const float* src = (const float*)d_in[0];   // [16, 4096, 3]
    const float* tgt = (const float*)d_in[1];   // [16, 4096, 3]
    const float* w   = (const float*)d_in[2];   // [16]

    static bool attr_set = false;
    if (!attr_set) {
        cudaFuncSetAttribute(bin_kernel,
            cudaFuncAttributeMaxDynamicSharedMemorySize, SMEM_BIN);
        cudaFuncSetAttribute(solve_kernel,
            cudaFuncAttributeMaxDynamicSharedMemorySize, SMEM_SOLVE);
        cudaFuncSetAttribute(tail_kernel,
            cudaFuncAttributeMaxDynamicSharedMemorySize, TAIL_SMEM);
        attr_set = true;
    }

    bin_kernel<<<2 * B_, BIN_THREADS, SMEM_BIN>>>(src, tgt);
    solve_kernel<<<SBLOCKS, STHREADS, SMEM_SOLVE>>>();
    tail_kernel<<<2 * B_, STHREADS, TAIL_SMEM>>>();
    fin1_kernel<<<2 * B_, 256>>>(w);
    fin2_kernel<<<1, 32>>>((float*)d_out);
}

// round 17
// speedup vs baseline: 1.0400x; 1.0400x over previous
#include <cuda_runtime.h>
#include <cfloat>
#include <climits>

// Batched Chamfer loss: z-sorted points + rank-probe upper bound + provable
// z-window pruning. Inner loops are IDENTICAL in shape to the proven dense
// brute-force kernel: warp-uniform trip counts, broadcast loads,
// 3 FFMA + 1 FMNMX per eval. B=16, N=M=4096.
//
// bin_kernel:  per (set,b): 1D z-binning into 256 slabs -> z-sorted folded
//              points (-2x,-2y,-2z,|t|^2) + slab starts.
// solve_kernel: one thread per query, queries in z-sorted order.
//   probe:  warp scans db rank-window [wb-64, wb+96) (dense, warp-uniform,
//           actual points -> valid upper bound d_ub).
//   window: r = sqrt(d_ub)*(1+2e-4)+1e-5; points with |dz|>r have d^2>d_ub,
//           so scanning slabs covering [qz-r, qz+r] (warp union) is EXACT.
//           Block stages its union window in smem; warp dense-scans its range.
// fin_kernel: deterministic reduction of 256 weighted block partials.

constexpr int   B_    = 16;
constexpr int   N_    = 4096;
constexpr int   SLABS = 256;
constexpr float ZLO_  = -4.0f;
constexpr float SINV  = 32.0f;          // SLABS / (4 - (-4))
constexpr int   CAP   = 2560;           // staged block window cap (float4)

constexpr int BIN_T   = 512;
constexpr int SOLVE_T = 512;
constexpr int QBLK    = N_ / SOLVE_T;   // 8 solve blocks per (set,b)
constexpr int NPART   = 2 * B_ * QBLK;  // 256

__device__ float4 g_binned[2 * B_ * N_];        // z-sorted folded points
__device__ int    g_starts[2 * B_ * (SLABS + 1)];
__device__ float  g_partial[NPART];

__device__ __forceinline__ int slab_of(float z) {
    int s = (int)floorf((z - ZLO_) * SINV);
    return min(max(s, 0), SLABS - 1);
}

// ---------------- 1D z-binning ----------------

__global__ void __launch_bounds__(BIN_T)
bin_kernel(const float* __restrict__ src, const float* __restrict__ tgt)
{
    __shared__ int scnt[SLABS];         // counts -> exclusive starts -> cursors
    __shared__ int swsum[8];

    const int sb  = blockIdx.x;         // set*16 + b
    const int set = sb >> 4, b = sb & 15;
    const float4* __restrict__ g4 =
        (const float4*)((set == 0 ? src : tgt) + (size_t)b * N_ * 3);
    const int t = threadIdx.x, lane = t & 31, wid = t >> 5;

    if (t < SLABS) scnt[t] = 0;
    __syncthreads();

    // Thread owns 8 consecutive points = 6 consecutive float4 (coalesced).
    float4 v[6];
#pragma unroll
    for (int i = 0; i < 6; ++i) v[i] = g4[t * 6 + i];
    float f[24];
#pragma unroll
    for (int i = 0; i < 6; ++i) {
        f[i * 4 + 0] = v[i].x; f[i * 4 + 1] = v[i].y;
        f[i * 4 + 2] = v[i].z; f[i * 4 + 3] = v[i].w;
    }
    int ps[8];
#pragma unroll
    for (int r = 0; r < 8; ++r) {
        ps[r] = slab_of(f[3 * r + 2]);
        atomicAdd(&scnt[ps[r]], 1);
    }
    __syncthreads();

    // Exclusive scan over 256 slabs (first 256 threads = 8 warps).
    int c = 0, incl = 0;
    if (t < SLABS) {
        c = scnt[t];
        incl = c;
#pragma unroll
        for (int off = 1; off < 32; off <<= 1) {
            const int u = __shfl_up_sync(0xffffffffu, incl, off);
            if (lane >= off) incl += u;
        }
        if (lane == 31) swsum[wid] = incl;
    }
    __syncthreads();
    if (t < 32) {
        const int u = (lane < 8) ? swsum[lane] : 0;
        int inc2 = u;
#pragma unroll
        for (int off = 1; off < 8; off <<= 1) {
            const int w = __shfl_up_sync(0xffffffffu, inc2, off);
            if (lane >= off) inc2 += w;
        }
        if (lane < 8) swsum[lane] = inc2 - u;   // exclusive warp offsets
    }
    __syncthreads();
    if (t < SLABS) {
        const int excl = swsum[wid] + incl - c;
        g_starts[sb * (SLABS + 1) + t] = excl;
        scnt[t] = excl;                          // becomes write cursor
    }
    if (t == 0) g_starts[sb * (SLABS + 1) + SLABS] = N_;
    __syncthreads();

    // Scatter folded points into z-sorted order.
#pragma unroll
    for (int r = 0; r < 8; ++r) {
        const float x = f[3 * r + 0], y = f[3 * r + 1], z = f[3 * r + 2];
        const int pos = atomicAdd(&scnt[ps[r]], 1);
        g_binned[sb * N_ + pos] =
            make_float4(-2.0f * x, -2.0f * y, -2.0f * z,
                        x * x + y * y + z * z);
    }
}

// ---------------- solve ----------------

__global__ void __launch_bounds__(SOLVE_T)
solve_kernel(const float* __restrict__ weights)
{
    __shared__ float4 s_db[CAP];        // 40 KB staged block window
    __shared__ float  s_red[SOLVE_T];
    __shared__ int    s_bp0, s_bp1;

    const int sb   = blockIdx.y;        // query (set,b)
    const int dbsb = sb ^ 16;           // database (set,b)
    const int tid  = threadIdx.x, lane = tid & 31;
    const int pos  = blockIdx.x * SOLVE_T + tid;

    const float4* __restrict__ pts    = g_binned + dbsb * N_;
    const int*    __restrict__ starts = g_starts + dbsb * (SLABS + 1);

    if (tid == 0) { s_bp0 = INT_MAX; s_bp1 = 0; }

    const float4 qt = g_binned[sb * N_ + pos];
    const float qx = -0.5f * qt.x, qy = -0.5f * qt.y, qz = -0.5f * qt.z;
    const float q2 = qt.w;

    // ---- probe: dense warp-uniform scan of db rank window ----
    const int wb  = blockIdx.x * SOLVE_T + (tid >> 5) * 32;
    const int plo = max(wb - 64, 0), phi = min(wb + 96, N_);
    float vmin = FLT_MAX;               // folded (= d^2 - q2)
#pragma unroll 4
    for (int p = plo; p < phi; ++p) {
        const float4 tp = pts[p];       // broadcast LDG
        vmin = fminf(vmin, fmaf(qx, tp.x, fmaf(qy, tp.y, fmaf(qz, tp.z, tp.w))));
    }

    // ---- window: r from the upper bound; warp union; slab range ----
    const float dub = fmaxf(q2 + vmin, 0.0f);
    const float r   = sqrtf(dub) * 1.0002f + 1e-5f;
    float zlo = qz - r, zhi = qz + r;
#pragma unroll
    for (int off = 16; off > 0; off >>= 1) {
        zlo = fminf(zlo, __shfl_xor_sync(0xffffffffu, zlo, off));
        zhi = fmaxf(zhi, __shfl_xor_sync(0xffffffffu, zhi, off));
    }
    const int wp0 = starts[slab_of(zlo)];
    const int wp1 = starts[slab_of(zhi) + 1];

    __syncthreads();                    // orders s_bp init before atomics
    if (lane == 0) { atomicMin(&s_bp0, wp0); atomicMax(&s_bp1, wp1); }
    __syncthreads();
    const int bp0 = s_bp0;
    const int C   = s_bp1 - bp0;

    // Stage block union window in smem (C is block-uniform).
    const float4* base;
    int off0;
    if (C <= CAP) {
        for (int i = tid; i < C; i += SOLVE_T)
            s_db[i] = pts[bp0 + i];
        base = s_db; off0 = bp0;
    } else {                            // rare overflow: scan global directly
        base = pts; off0 = 0;
    }
    __syncthreads();

    // ---- main: dense warp-uniform scan of the warp's window ----
#pragma unroll 4
    for (int p = wp0; p < wp1; ++p) {
        const float4 tp = base[p - off0];   // broadcast LDS (or LDG)
        vmin = fminf(vmin, fmaf(qx, tp.x, fmaf(qy, tp.y, fmaf(qz, tp.z, tp.w))));
    }

    // ---- deterministic block reduction, weight folded ----
    s_red[tid] = fmaxf(q2 + vmin, 0.0f);
    __syncthreads();
#pragma unroll
    for (int st = SOLVE_T / 2; st > 0; st >>= 1) {
        if (tid < st) s_red[tid] += s_red[tid + st];
        __syncthreads();
    }
    if (tid == 0)
        g_partial[sb * QBLK + blockIdx.x] = s_red[0] * weights[sb & 15];
}

// ---------------- finalize ----------------

__global__ void __launch_bounds__(NPART)
fin_kernel(float* __restrict__ out)
{
    const int t = threadIdx.x;          // 0..255
    __shared__ float s[NPART];
    s[t] = g_partial[t];
    __syncthreads();
#pragma unroll
    for (int st = NPART / 2; st > 0; st >>= 1) {
        if (t < st) s[t] += s[t + st];
        __syncthreads();
    }
    if (t == 0) out[0] = s[0] * (1.0f / (16.0f * 4096.0f));
}

extern "C" void kernel_launch(void* const* d_in, const int* in_sizes, int n_in,
                              void* d_out, int out_size)
{
    const float* src = (const float*)d_in[0];   // [16, 4096, 3]
    const float* tgt = (const float*)d_in[1];   // [16, 4096, 3]
    const float* w   = (const float*)d_in[2];   // [16]

    bin_kernel<<<2 * B_, BIN_T>>>(src, tgt);
    solve_kernel<<<dim3(QBLK, 2 * B_), SOLVE_T>>>(w);
    fin_kernel<<<1, NPART>>>((float*)d_out);
}